// round 2
// baseline (speedup 1.0000x reference)
#include <cuda_runtime.h>

// Problem constants
#define BB    8
#define C     128
#define W     256
#define H     256
#define NPIX  (W*H)          // 65536 pixels per image
#define NB7   64             // blocks covering batch 7

// Output buffer layout (concatenated f32, raw reshapes):
//  [0,256)                centersIterout [2,128]
//  [256, +BB*NPIX)        labelsout      [8,1,256,256]
//  [.., +BB*2*NPIX)       labels_onehot  [8,2,256,256]  (interleaved pairs per pixel)
//  [.., +BB*2*NPIX)       dist2center    [8,2,256,256]  (interleaved pairs per pixel)
//  [.., +BB*NPIX)         labelTinit     (== labelsout)
#define OFF_CENTERS 0
#define OFF_LABELS  256
#define OFF_ONEHOT  (OFF_LABELS + BB*NPIX)
#define OFF_DIST    (OFF_ONEHOT + BB*2*NPIX)
#define OFF_LABELT  (OFF_DIST   + BB*2*NPIX)

// Scratch (__device__ globals; no allocation allowed).
// g_part: per-b7-block per-channel sums, unique slots -> overwrite, no zeroing.
//   layout: [slot][0..127] = label0 channel sums, [slot][128..255] = label1 sums
__device__ float g_part[NB7 * 256];
__device__ int   g_cnt[NB7];     // label==1 count per b7 block (overwrite)
__device__ int   g_arrive = 0;   // arrival counter; last epilogue block resets to 0

// ---------------------------------------------------------------------------
// Single fused kernel.
// Grid: 512 blocks x 256 threads. Block blk: batch b = blk>>6, tile = blk&63,
// covering pixels [tile*1024, tile*1024+1024). 4 pixels (1 float4) per thread.
// Pass 1 (all blocks): dots vs both centers, labels, all large outputs.
// Pass 2 (b==7 blocks only): per-channel masked sums over the block's own
//   tile (L1/L2-warm re-read), written to unique slots; last block to finish
//   reduces all 64 slots and writes the 256-float center epilogue.
// ---------------------------------------------------------------------------
__global__ void __launch_bounds__(256) k_fused(const float* __restrict__ F,
                                               const float* __restrict__ Cinit,
                                               float* __restrict__ out) {
    __shared__ float sc[2*C];          // centers
    __shared__ float slab[4*256];      // this block's 1024 labels (as float)
    __shared__ int   wred[8];
    __shared__ int   s_done;

    int t = threadIdx.x;
    sc[t] = Cinit[t];
    __syncthreads();

    int blk  = blockIdx.x;             // 0..511
    int b    = blk >> 6;
    int slot = blk & 63;
    int p4   = slot * 256 + t;         // float4-pixel index within image
    int n0   = p4 << 2;

    const float4* Fb = reinterpret_cast<const float4*>(F + (size_t)b * C * NPIX);

    float4 a0 = make_float4(0.f,0.f,0.f,0.f);
    float4 a1 = make_float4(0.f,0.f,0.f,0.f);

    #pragma unroll 8
    for (int ch = 0; ch < C; ch++) {
        float4 f = Fb[ch * (NPIX/4) + p4];
        float c0 = sc[ch];
        float c1 = sc[C + ch];
        a0.x += f.x*c0; a0.y += f.y*c0; a0.z += f.z*c0; a0.w += f.w*c0;
        a1.x += f.x*c1; a1.y += f.y*c1; a1.z += f.z*c1; a1.w += f.w*c1;
    }

    // dists = 0.5*(1 - dot)
    float d0x = 0.5f - 0.5f*a0.x, d1x = 0.5f - 0.5f*a1.x;
    float d0y = 0.5f - 0.5f*a0.y, d1y = 0.5f - 0.5f*a1.y;
    float d0z = 0.5f - 0.5f*a0.z, d1z = 0.5f - 0.5f*a1.z;
    float d0w = 0.5f - 0.5f*a0.w, d1w = 0.5f - 0.5f*a1.w;

    // argmin: label 1 only on strict d1 < d0
    int lx = d1x < d0x, ly = d1y < d0y, lz = d1z < d0z, lw = d1w < d0w;
    float4 lab = make_float4((float)lx, (float)ly, (float)lz, (float)lw);

    // labelsout + labelTinit (identical)
    *reinterpret_cast<float4*>(out + OFF_LABELS + (size_t)b*NPIX + n0) = lab;
    *reinterpret_cast<float4*>(out + OFF_LABELT + (size_t)b*NPIX + n0) = lab;

    // one-hot, interleaved pairs per pixel
    float4* outO = reinterpret_cast<float4*>(out + OFF_ONEHOT + (size_t)b*2*NPIX + 2*n0);
    outO[0] = make_float4(1.f - lab.x, lab.x, 1.f - lab.y, lab.y);
    outO[1] = make_float4(1.f - lab.z, lab.z, 1.f - lab.w, lab.w);

    // dist2center, interleaved pairs per pixel
    float4* outD = reinterpret_cast<float4*>(out + OFF_DIST + (size_t)b*2*NPIX + 2*n0);
    outD[0] = make_float4(d0x, d1x, d0y, d1y);
    outD[1] = make_float4(d0z, d1z, d0w, d1w);

    if (b != BB - 1) return;

    // ---------------- Pass 2: batch-7 masked channel sums ----------------
    float4* sl4 = reinterpret_cast<float4*>(slab);
    sl4[t] = lab;

    // label==1 count for this block's 1024 pixels
    int wid = t >> 5, lane = t & 31;
    {
        int s = lx + ly + lz + lw;
        #pragma unroll
        for (int o = 16; o > 0; o >>= 1)
            s += __shfl_down_sync(0xffffffffu, s, o);
        if (lane == 0) wred[wid] = s;
    }
    __syncthreads();
    if (t == 0) {
        int v = 0;
        #pragma unroll
        for (int i = 0; i < 8; i++) v += wred[i];
        g_cnt[slot] = v;
    }

    // Each warp owns 16 channels; per channel sum 1024 pixels (L1/L2-warm).
    const float4* F7 = reinterpret_cast<const float4*>(F + (size_t)(BB-1) * C * NPIX);
    int base4 = slot * 256;
    for (int j = 0; j < 16; j++) {
        int ch = wid + 8*j;
        const float4* row = F7 + (size_t)ch * (NPIX/4) + base4;
        float sa = 0.f, s1 = 0.f;
        #pragma unroll
        for (int i = 0; i < 8; i++) {
            float4 f = row[i*32 + lane];
            float4 l = sl4[i*32 + lane];
            sa += f.x + f.y + f.z + f.w;
            s1 += f.x*l.x + f.y*l.y + f.z*l.z + f.w*l.w;
        }
        #pragma unroll
        for (int o = 16; o > 0; o >>= 1) {
            sa += __shfl_down_sync(0xffffffffu, sa, o);
            s1 += __shfl_down_sync(0xffffffffu, s1, o);
        }
        if (lane == 0) {
            g_part[slot*256 + ch]       = sa - s1;   // label 0 sum
            g_part[slot*256 + 128 + ch] = s1;        // label 1 sum
        }
    }

    // ---------------- Last b7-block does the epilogue ----------------
    __syncthreads();               // all slot writes done (program order per block)
    if (t == 0) {
        __threadfence();           // publish this block's g_part/g_cnt
        int old = atomicAdd(&g_arrive, 1);
        s_done = (old == NB7 - 1);
    }
    __syncthreads();
    if (!s_done) return;

    __threadfence();               // acquire: see all blocks' slots
    // count
    int cnt = 0;
    #pragma unroll 8
    for (int s = 0; s < NB7; s++) cnt += g_cnt[s];
    // per-thread channel sum over 64 slots
    float sum = 0.f;
    #pragma unroll 8
    for (int s = 0; s < NB7; s++) sum += g_part[s*256 + t];

    int k = t >> 7;
    float num = (k ? (float)cnt : (float)(NPIX - cnt)) + 1.0f;
    float mean = sum / num;
    float ci = sc[t];
    out[OFF_CENTERS + t] = ci + 0.001f * (mean - ci);

    if (t == 0) g_arrive = 0;      // reset for next graph replay
}

// ---------------------------------------------------------------------------
extern "C" void kernel_launch(void* const* d_in, const int* in_sizes, int n_in,
                              void* d_out, int out_size) {
    const float* F     = (const float*)d_in[0];   // FeatureT [8,128,256,256]
    const float* Cinit = (const float*)d_in[1];   // centerInit [2,128]
    float* out = (float*)d_out;
    (void)in_sizes; (void)n_in; (void)out_size;

    k_fused<<<512, 256>>>(F, Cinit, out);
}

// round 3
// speedup vs baseline: 1.3666x; 1.3666x over previous
#include <cuda_runtime.h>
#include <cstdint>

// Problem constants
#define BB    8
#define C     128
#define W     256
#define H     256
#define NPIX  (W*H)          // 65536 pixels per image

// Output buffer layout (concatenated f32, raw reshapes):
//  [0,256)                centersIterout [2,128]
//  [256, +BB*NPIX)        labelsout      [8,1,256,256]
//  [.., +BB*2*NPIX)       labels_onehot  [8,2,256,256]  (interleaved pairs per pixel)
//  [.., +BB*2*NPIX)       dist2center    [8,2,256,256]  (interleaved pairs per pixel)
//  [.., +BB*NPIX)         labelTinit     (== labelsout)
#define OFF_CENTERS 0
#define OFF_LABELS  256
#define OFF_ONEHOT  (OFF_LABELS + BB*NPIX)
#define OFF_DIST    (OFF_ONEHOT + BB*2*NPIX)
#define OFF_LABELT  (OFF_DIST   + BB*2*NPIX)

// Scratch (__device__ globals; no allocations allowed). All overwrite-slot
// semantics -> no zero-init kernel needed.
// g_mask: batch-7 labels as bits. One uint4 per warp of 32 float4-pixels:
//   for float4 index j (0..16383), word = g_mask[j>>5], lane = j&31,
//   label(pixel 4j+c) = bit lane of component c.
__device__ uint4 g_mask[512];
// g_part[(k*128+ch)*8 + tile]: per-tile per-channel label-k sums (batch 7)
__device__ float g_part[256 * 8];
__device__ int   g_arrive = 0;   // k_centers arrival counter; last block resets

// ---------------------------------------------------------------------------
// Kernel 1: fused distance + label + all large outputs.
// Grid: 512 blocks x 256 threads. Block blk: b = blk>>6, tile slot = blk&63,
// 1 float4 (4 pixels) per thread.
// Batches 0..6: streaming loads/stores (don't pollute L2).
// Batch 7: normal F loads (keep 32MB in L2 for k_centers) + label ballot mask.
// ---------------------------------------------------------------------------
template <bool STREAM>
__device__ __forceinline__ void dot_loop(const float4* __restrict__ Fb, int p4,
                                         const float* __restrict__ sc,
                                         float4& a0, float4& a1) {
    #pragma unroll 8
    for (int ch = 0; ch < C; ch++) {
        float4 f = STREAM ? __ldcs(&Fb[ch * (NPIX/4) + p4])
                          : Fb[ch * (NPIX/4) + p4];
        float c0 = sc[ch];
        float c1 = sc[C + ch];
        a0.x += f.x*c0; a0.y += f.y*c0; a0.z += f.z*c0; a0.w += f.w*c0;
        a1.x += f.x*c1; a1.y += f.y*c1; a1.z += f.z*c1; a1.w += f.w*c1;
    }
}

__global__ void __launch_bounds__(256) k_main(const float* __restrict__ F,
                                              const float* __restrict__ Cinit,
                                              float* __restrict__ out) {
    __shared__ float sc[2*C];
    int t = threadIdx.x;
    sc[t] = Cinit[t];
    __syncthreads();

    int blk  = blockIdx.x;             // 0..511
    int b    = blk >> 6;
    int slot = blk & 63;
    int p4   = slot * 256 + t;         // float4-pixel index within image
    int n0   = p4 << 2;

    const float4* Fb = reinterpret_cast<const float4*>(F + (size_t)b * C * NPIX);

    float4 a0 = make_float4(0.f,0.f,0.f,0.f);
    float4 a1 = make_float4(0.f,0.f,0.f,0.f);
    if (b == BB - 1) dot_loop<false>(Fb, p4, sc, a0, a1);
    else             dot_loop<true >(Fb, p4, sc, a0, a1);

    // dists = 0.5*(1 - dot)
    float d0x = 0.5f - 0.5f*a0.x, d1x = 0.5f - 0.5f*a1.x;
    float d0y = 0.5f - 0.5f*a0.y, d1y = 0.5f - 0.5f*a1.y;
    float d0z = 0.5f - 0.5f*a0.z, d1z = 0.5f - 0.5f*a1.z;
    float d0w = 0.5f - 0.5f*a0.w, d1w = 0.5f - 0.5f*a1.w;

    // argmin: label 1 only on strict d1 < d0
    int lx = d1x < d0x, ly = d1y < d0y, lz = d1z < d0z, lw = d1w < d0w;
    float4 lab = make_float4((float)lx, (float)ly, (float)lz, (float)lw);

    // All big outputs are never re-read -> streaming stores.
    __stcs(reinterpret_cast<float4*>(out + OFF_LABELS + (size_t)b*NPIX + n0), lab);
    __stcs(reinterpret_cast<float4*>(out + OFF_LABELT + (size_t)b*NPIX + n0), lab);

    float4* outO = reinterpret_cast<float4*>(out + OFF_ONEHOT + (size_t)b*2*NPIX + 2*n0);
    __stcs(outO + 0, make_float4(1.f - lab.x, lab.x, 1.f - lab.y, lab.y));
    __stcs(outO + 1, make_float4(1.f - lab.z, lab.z, 1.f - lab.w, lab.w));

    float4* outD = reinterpret_cast<float4*>(out + OFF_DIST + (size_t)b*2*NPIX + 2*n0);
    __stcs(outD + 0, make_float4(d0x, d1x, d0y, d1y));
    __stcs(outD + 1, make_float4(d0z, d1z, d0w, d1w));

    // Batch 7: publish labels as a bitmask (one uint4 per warp).
    if (b == BB - 1) {
        unsigned bx = __ballot_sync(0xffffffffu, lx);
        unsigned by = __ballot_sync(0xffffffffu, ly);
        unsigned bz = __ballot_sync(0xffffffffu, lz);
        unsigned bw = __ballot_sync(0xffffffffu, lw);
        if ((t & 31) == 0) g_mask[p4 >> 5] = make_uint4(bx, by, bz, bw);
    }
}

// ---------------------------------------------------------------------------
// Kernel 2: batch-7 per-channel masked sums + epilogue.
// Grid: dim3(128 ch, 8 tiles) x 256 threads; 8 float4/thread (32KB F per block,
// largely L2-resident thanks to k_main's cache steering). Labels come from the
// 8KB bitmask. Last-arriving block reduces tiles, popcounts the mask for the
// label-1 count, and writes centersIterout. Counter self-resets for replay.
// ---------------------------------------------------------------------------
__global__ void __launch_bounds__(256) k_centers(const float* __restrict__ F,
                                                 const float* __restrict__ Cinit,
                                                 float* __restrict__ out) {
    __shared__ float wa[8], w1[8];
    __shared__ int   wc[8];
    __shared__ int   s_done, s_cnt;

    int ch   = blockIdx.x;          // 0..127
    int tile = blockIdx.y;          // 0..7
    int t    = threadIdx.x;
    int wid  = t >> 5, lane = t & 31;

    const float4* Fp = reinterpret_cast<const float4*>(
        F + ((size_t)(BB-1) * C + ch) * NPIX);
    int base = tile * 2048;         // float4 index base (8192 pixels per tile)

    float sa = 0.f, s1 = 0.f;
    #pragma unroll
    for (int i = 0; i < 8; i++) {
        int j = base + i*256 + t;           // j&31 == lane
        float4 f = Fp[j];
        uint4  m = g_mask[j >> 5];
        float mx = (float)((m.x >> lane) & 1u);
        float my = (float)((m.y >> lane) & 1u);
        float mz = (float)((m.z >> lane) & 1u);
        float mw = (float)((m.w >> lane) & 1u);
        sa += f.x + f.y + f.z + f.w;
        s1 += f.x*mx + f.y*my + f.z*mz + f.w*mw;
    }

    #pragma unroll
    for (int o = 16; o > 0; o >>= 1) {
        sa += __shfl_down_sync(0xffffffffu, sa, o);
        s1 += __shfl_down_sync(0xffffffffu, s1, o);
    }
    if (lane == 0) { wa[wid] = sa; w1[wid] = s1; }
    __syncthreads();
    if (t == 0) {
        float va = 0.f, v1 = 0.f;
        #pragma unroll
        for (int i = 0; i < 8; i++) { va += wa[i]; v1 += w1[i]; }
        g_part[(ch)       * 8 + tile] = va - v1;   // label 0 sum
        g_part[(C + ch)   * 8 + tile] = v1;        // label 1 sum
    }

    // ---- arrival; last block does the epilogue ----
    __syncthreads();
    if (t == 0) {
        __threadfence();
        int old = atomicAdd(&g_arrive, 1);
        s_done = (old == 128*8 - 1);
    }
    __syncthreads();
    if (!s_done) return;
    __threadfence();

    // label-1 count via mask popcount (2048 words / 256 threads = 2 uint4 each)
    {
        uint4 m0 = g_mask[2*t], m1 = g_mask[2*t + 1];
        int c = __popc(m0.x) + __popc(m0.y) + __popc(m0.z) + __popc(m0.w)
              + __popc(m1.x) + __popc(m1.y) + __popc(m1.z) + __popc(m1.w);
        #pragma unroll
        for (int o = 16; o > 0; o >>= 1)
            c += __shfl_down_sync(0xffffffffu, c, o);
        if (lane == 0) wc[wid] = c;
        __syncthreads();
        if (t == 0) {
            int v = 0;
            #pragma unroll
            for (int i = 0; i < 8; i++) v += wc[i];
            s_cnt = v;
        }
        __syncthreads();
    }

    // reduce the 8 tile slots for this thread's (k,ch) and write centers
    float sum = 0.f;
    #pragma unroll
    for (int i = 0; i < 8; i++) sum += __ldcg(&g_part[t*8 + i]);

    int k = t >> 7;
    float num = (k ? (float)s_cnt : (float)(NPIX - s_cnt)) + 1.0f;
    float mean = sum / num;
    float ci = Cinit[t];
    out[OFF_CENTERS + t] = ci + 0.001f * (mean - ci);

    if (t == 0) g_arrive = 0;       // reset for next graph replay
}

// ---------------------------------------------------------------------------
extern "C" void kernel_launch(void* const* d_in, const int* in_sizes, int n_in,
                              void* d_out, int out_size) {
    const float* F     = (const float*)d_in[0];   // FeatureT [8,128,256,256]
    const float* Cinit = (const float*)d_in[1];   // centerInit [2,128]
    float* out = (float*)d_out;
    (void)in_sizes; (void)n_in; (void)out_size;

    k_main<<<512, 256>>>(F, Cinit, out);
    k_centers<<<dim3(C, 8), 256>>>(F, Cinit, out);
}